// round 1
// baseline (speedup 1.0000x reference)
#include <cuda_runtime.h>

#define NB 4
#define NC 64
#define NH 256
#define NW 256
#define NPIX 65536
#define NWH 128
#define NPH 32768
#define NHEADS 4
#define ND 16
#define NC2 128
#define NC4 256

// ---- scratch (device globals: allocation-free rule) ----
static __device__ float g_q1[NB*NC*NPIX];
static __device__ float g_k1[NB*NC*NPIX];
static __device__ float g_v1[NB*NC*NPIX];
static __device__ float g_qs[NB*NC*NPH];
static __device__ float g_ks[NB*NC*NPH];
static __device__ float g_vs[NB*NC*NPH];
static __device__ float g_att[NB*NC*NPH];      // squeezed attention output (nonanchor positions)
static __device__ float g_m1v[NB*NC4*NPIX];
static __device__ float g_m2v[NB*NC4*NPIX];
static __device__ float g_kmax[NB*NC];
static __device__ float g_ksum[NB*NC];
static __device__ float g_ctx[NB*NHEADS*ND*ND];
static __device__ float g_rwt[NC*25*NC2];      // r_w transposed -> [ci][tap][co]
static __device__ float g_m1wt[NC2*NC4];       // m1_w transposed -> [ci][co]
static __device__ float g_m3wt[NC4*NC2];       // m3_w transposed -> [ci][co]

__device__ __forceinline__ float gelu_f(float x){
    return 0.5f*x*(1.0f+erff(x*0.70710678118654752440f));
}

// ---------------- K0: weight transposes (cheap, per launch) ----------------
__global__ void k_prep(const float* __restrict__ rw, const float* __restrict__ m1w,
                       const float* __restrict__ m3w){
    int i = blockIdx.x*256 + threadIdx.x;
    if (i < 128*64*25){            // r_w [co][ci][tap] -> [ci][tap][co]
        int co = i/1600; int r = i - co*1600; int ci = r/25; int tap = r - ci*25;
        g_rwt[(ci*25+tap)*NC2 + co] = rw[i];
    }
    if (i < 256*128){              // m1_w [co][ci] -> [ci][co]
        int co = i>>7, ci = i&127;
        g_m1wt[ci*NC4 + co] = m1w[i];
    }
    if (i < 128*256){              // m3_w [co][ci] -> [ci][co]
        int co = i>>8, ci = i&255;
        g_m3wt[ci*NC2 + co] = m3w[i];
    }
}

// ---------------- K1: fused q/k/v 1x1 convs ----------------
// At even-parity pixels only q gets real data (x1_na keeps even), odd-parity only k.
// The other tensor at that pixel is just its bias. v is dense from x2.
__global__ __launch_bounds__(256) void k_qkv1(
    const float* __restrict__ x1, const float* __restrict__ x2,
    const float* __restrict__ qw, const float* __restrict__ qb,
    const float* __restrict__ kw, const float* __restrict__ kb,
    const float* __restrict__ vw, const float* __restrict__ vb)
{
    __shared__ float4 Wsm[3072];   // [Wq | Wk | Wv], each 64x64 floats = 1024 float4
    int tid = threadIdx.x;
    for (int i = tid; i < 1024; i += 256){
        Wsm[i]       = ((const float4*)qw)[i];
        Wsm[1024+i]  = ((const float4*)kw)[i];
        Wsm[2048+i]  = ((const float4*)vw)[i];
    }
    __syncthreads();

    int pix = blockIdx.x*256 + tid;          // grid = 1024 blocks -> B*N pixels
    int b = pix >> 16; int ij = pix & 65535;
    int i_ = ij >> 8, j_ = ij & 255;
    int par = (i_ + j_) & 1;                 // 0 = nonanchor(q), 1 = anchor(k)
    size_t base = (size_t)b*NC*NPIX + ij;

    float xr[64];
    const float* xin = x1 + base;
    #pragma unroll
    for (int c = 0; c < 64; c++) xr[c] = xin[(size_t)c*NPIX];

    const float4* wb4 = par ? (Wsm + 1024) : Wsm;
    float* dst = par ? g_k1 : g_q1;
    float* oth = par ? g_q1 : g_k1;
    const float* bd = par ? kb : qb;
    const float* bo = par ? qb : kb;

    #pragma unroll 4
    for (int co = 0; co < 64; co++){
        float acc = bd[co];
        #pragma unroll
        for (int c4 = 0; c4 < 16; c4++){
            float4 w = wb4[co*16 + c4];
            acc = fmaf(w.x, xr[4*c4+0], acc);
            acc = fmaf(w.y, xr[4*c4+1], acc);
            acc = fmaf(w.z, xr[4*c4+2], acc);
            acc = fmaf(w.w, xr[4*c4+3], acc);
        }
        dst[base + (size_t)co*NPIX] = acc;
        oth[base + (size_t)co*NPIX] = bo[co];
    }

    const float* x2in = x2 + base;
    #pragma unroll
    for (int c = 0; c < 64; c++) xr[c] = x2in[(size_t)c*NPIX];
    #pragma unroll 4
    for (int co = 0; co < 64; co++){
        float acc = vb[co];
        #pragma unroll
        for (int c4 = 0; c4 < 16; c4++){
            float4 w = Wsm[2048 + co*16 + c4];
            acc = fmaf(w.x, xr[4*c4+0], acc);
            acc = fmaf(w.y, xr[4*c4+1], acc);
            acc = fmaf(w.z, xr[4*c4+2], acc);
            acc = fmaf(w.w, xr[4*c4+3], acc);
        }
        g_v1[base + (size_t)co*NPIX] = acc;
    }
}

// ---------------- K2: depthwise 3x3 evaluated only at squeezed target positions ----------------
__global__ void k_dws(const float* __restrict__ q2w, const float* __restrict__ q2b,
                      const float* __restrict__ k2w, const float* __restrict__ k2b,
                      const float* __restrict__ v2w, const float* __restrict__ v2b)
{
    int z = blockIdx.y;
    const float* src; const float* w; const float* bias; float* dst; int asel;
    if (z == 0){ src=g_q1; w=q2w; bias=q2b; dst=g_qs; asel=0; }
    else if (z == 1){ src=g_k1; w=k2w; bias=k2b; dst=g_ks; asel=1; }
    else { src=g_v1; w=v2w; bias=v2b; dst=g_vs; asel=1; }

    int gid = blockIdx.x*256 + threadIdx.x;        // layout [bc][i][jp]
    int jp = gid & 127; int i_ = (gid>>7) & 255; int bc = gid >> 15;
    int c = bc & 63;
    int j_ = 2*jp + ((i_ & 1) ^ asel);             // full-grid column

    const float* s = src + (size_t)bc*NPIX;
    const float* wc = w + c*9;
    float acc = bias[c];
    #pragma unroll
    for (int di = -1; di <= 1; di++)
        #pragma unroll
        for (int dj = -1; dj <= 1; dj++){
            int ii = i_ + di, jj = j_ + dj;
            if (ii >= 0 && ii < NH && jj >= 0 && jj < NW)
                acc = fmaf(wc[(di+1)*3 + (dj+1)], s[ii*NW + jj], acc);
        }
    dst[gid] = acc;
}

// ---------------- K3: per-(b,c) max and sum-exp for k softmax ----------------
__global__ void k_kstats(){
    int row = blockIdx.x;                     // 0..255
    const float* s = g_ks + (size_t)row*NPH;
    int tid = threadIdx.x;
    __shared__ float red[256];
    float m = -1e30f;
    for (int i = tid; i < NPH; i += 256) m = fmaxf(m, s[i]);
    red[tid] = m; __syncthreads();
    for (int st = 128; st > 0; st >>= 1){ if (tid < st) red[tid] = fmaxf(red[tid], red[tid+st]); __syncthreads(); }
    m = red[0];
    __syncthreads();
    float sum = 0.f;
    for (int i = tid; i < NPH; i += 256) sum += __expf(s[i] - m);
    red[tid] = sum; __syncthreads();
    for (int st = 128; st > 0; st >>= 1){ if (tid < st) red[tid] += red[tid+st]; __syncthreads(); }
    if (tid == 0){ g_kmax[row] = m; g_ksum[row] = red[0]; }
}

__global__ void k_zero(){
    int i = blockIdx.x*256 + threadIdx.x;
    if (i < NB*NHEADS*ND*ND) g_ctx[i] = 0.f;
}

// ---------------- K4: ctx[b,h,d,e] = sum_n softmax(k)[d,n] * v[e,n] ----------------
__global__ __launch_bounds__(256) void k_ctx(){
    int bh = blockIdx.x;                 // 16
    int split = blockIdx.y;              // 16 splits of 2048
    int b = bh >> 2, hd = bh & 3;
    int crow = b*NC + hd*ND;
    int n0 = split * (NPH/16);

    __shared__ float ksm[16][65];
    __shared__ float vsm[16][65];
    __shared__ float kmx[16], kin[16];
    int tid = threadIdx.x;
    int d = tid & 15, e = tid >> 4;
    if (tid < 16){ kmx[tid] = g_kmax[crow + tid]; kin[tid] = 1.f / g_ksum[crow + tid]; }
    __syncthreads();

    float acc = 0.f;
    for (int nb = 0; nb < NPH/16; nb += 64){
        __syncthreads();
        for (int idx = tid; idx < 1024; idx += 256){
            int dd = idx >> 6, nn = idx & 63;
            int n = n0 + nb + nn;
            ksm[dd][nn] = __expf(g_ks[(size_t)(crow+dd)*NPH + n] - kmx[dd]) * kin[dd];
            vsm[dd][nn] = g_vs[(size_t)(crow+dd)*NPH + n];
        }
        __syncthreads();
        #pragma unroll
        for (int nn = 0; nn < 64; nn++)
            acc = fmaf(ksm[d][nn], vsm[e][nn], acc);
    }
    atomicAdd(&g_ctx[bh*256 + d*16 + e], acc);
}

// ---------------- K5: fused q-softmax(over d) + att = ctx^T @ q (squeezed layout) ----------------
__global__ void k_att(){
    int bh = blockIdx.y; int b = bh >> 2, hd = bh & 3;
    int pos = blockIdx.x*256 + threadIdx.x;     // < NPH
    __shared__ float ctxs[256];
    ctxs[threadIdx.x] = g_ctx[bh*256 + threadIdx.x];
    __syncthreads();

    size_t base = ((size_t)(b*NC + hd*ND))*NPH + pos;
    float qv[16];
    float mx = -1e30f;
    #pragma unroll
    for (int d = 0; d < 16; d++){ qv[d] = g_qs[base + (size_t)d*NPH]; mx = fmaxf(mx, qv[d]); }
    float s = 0.f;
    #pragma unroll
    for (int d = 0; d < 16; d++){ qv[d] = __expf(qv[d] - mx); s += qv[d]; }
    float inv = 1.f / s;
    #pragma unroll
    for (int e = 0; e < 16; e++){
        float a = 0.f;
        #pragma unroll
        for (int d = 0; d < 16; d++) a = fmaf(ctxs[d*16 + e], qv[d], a);
        g_att[base + (size_t)e*NPH] = a * inv;
    }
}

// ---------------- K6: 5x5 conv (64 -> 128) on checkerboard-sparse att ----------------
// att_full(i,j) = ((i+j)&1==0) ? att_sq[i][j>>1] : 0.
// Threads are grouped so each warp has uniform pixel parity -> only its 13/12 valid taps run.
__global__ __launch_bounds__(256) void k_conv5(const float* __restrict__ rb, float* __restrict__ out){
    __shared__ float attsm[1600];   // [8ci][20rows][10cols]
    __shared__ float wsm[6400];     // [8ci][25tap][32co]
    int tid = threadIdx.x;
    int b = blockIdx.z >> 2, cog = blockIdx.z & 3;
    int i0 = blockIdx.y*16, j0 = blockIdx.x*16;

    int p = tid >> 7;               // warp-uniform parity
    int id = tid & 127; int ty = id >> 3; int txp = id & 7;
    int tx = 2*txp + ((ty + p) & 1);

    int tc[5];
    #pragma unroll
    for (int kj = 0; kj < 5; kj++) tc[kj] = ((tx + kj - 2) >> 1) + 1;

    float acc[32];
    #pragma unroll
    for (int c = 0; c < 32; c++) acc[c] = 0.f;

    for (int cc0 = 0; cc0 < 64; cc0 += 8){
        __syncthreads();
        for (int idx = tid; idx < 1600; idx += 256){
            int ci = idx/200; int r2 = idx - ci*200; int rr = r2/10; int cl = r2 - rr*10;
            int grow = i0 - 2 + rr; int gcol = (j0 >> 1) - 1 + cl;
            float v = 0.f;
            if (grow >= 0 && grow < NH && gcol >= 0 && gcol < NWH)
                v = g_att[((size_t)(b*NC + cc0 + ci)*NH + grow)*NWH + gcol];
            attsm[idx] = v;
        }
        for (int idx = tid; idx < 6400; idx += 256){
            int col = idx & 31; int t2 = idx >> 5;   // t2 = ci*25+tap
            wsm[idx] = g_rwt[(size_t)(cc0*25 + t2)*NC2 + cog*32 + col];
        }
        __syncthreads();
        #pragma unroll 2
        for (int ci = 0; ci < 8; ci++){
            const float* A = attsm + ci*200 + ty*10;
            const float4* Wf = (const float4*)(wsm + ci*800);
            if (p == 0){
                static const int KI[13] = {0,0,0,1,1,2,2,2,3,3,4,4,4};
                static const int KJ[13] = {0,2,4,1,3,0,2,4,1,3,0,2,4};
                #pragma unroll
                for (int t = 0; t < 13; t++){
                    float a = A[KI[t]*10 + tc[KJ[t]]];
                    const float4* wp = Wf + (KI[t]*5 + KJ[t])*8;
                    #pragma unroll
                    for (int c4 = 0; c4 < 8; c4++){
                        float4 w = wp[c4];
                        acc[4*c4+0] = fmaf(a, w.x, acc[4*c4+0]);
                        acc[4*c4+1] = fmaf(a, w.y, acc[4*c4+1]);
                        acc[4*c4+2] = fmaf(a, w.z, acc[4*c4+2]);
                        acc[4*c4+3] = fmaf(a, w.w, acc[4*c4+3]);
                    }
                }
            } else {
                static const int KI2[12] = {0,0,1,1,1,2,2,3,3,3,4,4};
                static const int KJ2[12] = {1,3,0,2,4,1,3,0,2,4,1,3};
                #pragma unroll
                for (int t = 0; t < 12; t++){
                    float a = A[KI2[t]*10 + tc[KJ2[t]]];
                    const float4* wp = Wf + (KI2[t]*5 + KJ2[t])*8;
                    #pragma unroll
                    for (int c4 = 0; c4 < 8; c4++){
                        float4 w = wp[c4];
                        acc[4*c4+0] = fmaf(a, w.x, acc[4*c4+0]);
                        acc[4*c4+1] = fmaf(a, w.y, acc[4*c4+1]);
                        acc[4*c4+2] = fmaf(a, w.z, acc[4*c4+2]);
                        acc[4*c4+3] = fmaf(a, w.w, acc[4*c4+3]);
                    }
                }
            }
        }
    }
    int i_ = i0 + ty, j_ = j0 + tx;
    size_t ob = ((size_t)(b*NC2 + cog*32)*NH + i_)*NW + j_;
    #pragma unroll
    for (int c = 0; c < 32; c++)
        out[ob + (size_t)c*NPIX] = acc[c] + rb[cog*32 + c];
}

// ---------------- K7: m1 = gelu(1x1 conv 128->256) ----------------
__global__ __launch_bounds__(256) void k_gemm_m1(const float* __restrict__ X, const float* __restrict__ bias){
    __shared__ float wsm[16][64];
    __shared__ float xsm[16][64];
    int b = blockIdx.z; int co0 = blockIdx.y*64; int px0 = blockIdx.x*64;
    int tid = threadIdx.x; int tx = tid & 15, ty = tid >> 4;
    float acc[4][4];
    #pragma unroll
    for (int i = 0; i < 4; i++)
        #pragma unroll
        for (int j = 0; j < 4; j++) acc[i][j] = 0.f;

    for (int k0 = 0; k0 < NC2; k0 += 16){
        __syncthreads();
        for (int idx = tid; idx < 1024; idx += 256){
            int k = idx >> 6, c = idx & 63;
            wsm[k][c] = g_m1wt[(size_t)(k0+k)*NC4 + co0 + c];
            xsm[k][c] = X[((size_t)(b*NC2 + k0 + k))*NPIX + px0 + c];
        }
        __syncthreads();
        #pragma unroll
        for (int k = 0; k < 16; k++){
            float4 a  = *(const float4*)&wsm[k][ty*4];
            float4 x4 = *(const float4*)&xsm[k][tx*4];
            acc[0][0]=fmaf(a.x,x4.x,acc[0][0]); acc[0][1]=fmaf(a.x,x4.y,acc[0][1]);
            acc[0][2]=fmaf(a.x,x4.z,acc[0][2]); acc[0][3]=fmaf(a.x,x4.w,acc[0][3]);
            acc[1][0]=fmaf(a.y,x4.x,acc[1][0]); acc[1][1]=fmaf(a.y,x4.y,acc[1][1]);
            acc[1][2]=fmaf(a.y,x4.z,acc[1][2]); acc[1][3]=fmaf(a.y,x4.w,acc[1][3]);
            acc[2][0]=fmaf(a.z,x4.x,acc[2][0]); acc[2][1]=fmaf(a.z,x4.y,acc[2][1]);
            acc[2][2]=fmaf(a.z,x4.z,acc[2][2]); acc[2][3]=fmaf(a.z,x4.w,acc[2][3]);
            acc[3][0]=fmaf(a.w,x4.x,acc[3][0]); acc[3][1]=fmaf(a.w,x4.y,acc[3][1]);
            acc[3][2]=fmaf(a.w,x4.z,acc[3][2]); acc[3][3]=fmaf(a.w,x4.w,acc[3][3]);
        }
    }
    #pragma unroll
    for (int i = 0; i < 4; i++){
        int co = co0 + ty*4 + i;
        float bb = bias[co];
        float4 o;
        o.x = gelu_f(acc[i][0] + bb);
        o.y = gelu_f(acc[i][1] + bb);
        o.z = gelu_f(acc[i][2] + bb);
        o.w = gelu_f(acc[i][3] + bb);
        *(float4*)&g_m1v[((size_t)(b*NC4 + co))*NPIX + px0 + tx*4] = o;
    }
}

// ---------------- K8: m2 = gelu(depthwise 3x3 on 256 ch) ----------------
__global__ void k_m2dw(const float* __restrict__ w, const float* __restrict__ bias){
    int gid = blockIdx.x*256 + threadIdx.x;
    int j_ = gid & 255; int i_ = (gid >> 8) & 255; int bc = gid >> 16; int c = bc & 255;
    const float* s = g_m1v + (size_t)bc*NPIX;
    const float* wc = w + c*9;
    float acc = bias[c];
    #pragma unroll
    for (int di = -1; di <= 1; di++)
        #pragma unroll
        for (int dj = -1; dj <= 1; dj++){
            int ii = i_ + di, jj = j_ + dj;
            if (ii >= 0 && ii < NH && jj >= 0 && jj < NW)
                acc = fmaf(wc[(di+1)*3 + (dj+1)], s[ii*NW + jj], acc);
        }
    g_m2v[gid] = gelu_f(acc);
}

// ---------------- K9: out = attention + 1x1 conv 256->128 ----------------
__global__ __launch_bounds__(256) void k_gemm_m3(const float* __restrict__ bias, float* __restrict__ out){
    __shared__ float wsm[16][64];
    __shared__ float xsm[16][64];
    int b = blockIdx.z; int co0 = blockIdx.y*64; int px0 = blockIdx.x*64;
    int tid = threadIdx.x; int tx = tid & 15, ty = tid >> 4;
    float acc[4][4];
    #pragma unroll
    for (int i = 0; i < 4; i++)
        #pragma unroll
        for (int j = 0; j < 4; j++) acc[i][j] = 0.f;

    for (int k0 = 0; k0 < NC4; k0 += 16){
        __syncthreads();
        for (int idx = tid; idx < 1024; idx += 256){
            int k = idx >> 6, c = idx & 63;
            wsm[k][c] = g_m3wt[(size_t)(k0+k)*NC2 + co0 + c];
            xsm[k][c] = g_m2v[((size_t)(b*NC4 + k0 + k))*NPIX + px0 + c];
        }
        __syncthreads();
        #pragma unroll
        for (int k = 0; k < 16; k++){
            float4 a  = *(const float4*)&wsm[k][ty*4];
            float4 x4 = *(const float4*)&xsm[k][tx*4];
            acc[0][0]=fmaf(a.x,x4.x,acc[0][0]); acc[0][1]=fmaf(a.x,x4.y,acc[0][1]);
            acc[0][2]=fmaf(a.x,x4.z,acc[0][2]); acc[0][3]=fmaf(a.x,x4.w,acc[0][3]);
            acc[1][0]=fmaf(a.y,x4.x,acc[1][0]); acc[1][1]=fmaf(a.y,x4.y,acc[1][1]);
            acc[1][2]=fmaf(a.y,x4.z,acc[1][2]); acc[1][3]=fmaf(a.y,x4.w,acc[1][3]);
            acc[2][0]=fmaf(a.z,x4.x,acc[2][0]); acc[2][1]=fmaf(a.z,x4.y,acc[2][1]);
            acc[2][2]=fmaf(a.z,x4.z,acc[2][2]); acc[2][3]=fmaf(a.z,x4.w,acc[2][3]);
            acc[3][0]=fmaf(a.w,x4.x,acc[3][0]); acc[3][1]=fmaf(a.w,x4.y,acc[3][1]);
            acc[3][2]=fmaf(a.w,x4.z,acc[3][2]); acc[3][3]=fmaf(a.w,x4.w,acc[3][3]);
        }
    }
    #pragma unroll
    for (int i = 0; i < 4; i++){
        int co = co0 + ty*4 + i;
        float bb = bias[co];
        size_t ob = ((size_t)(b*NC2 + co))*NPIX + px0 + tx*4;
        float4 r = *(const float4*)&out[ob];
        float4 o;
        o.x = acc[i][0] + bb + r.x;
        o.y = acc[i][1] + bb + r.y;
        o.z = acc[i][2] + bb + r.z;
        o.w = acc[i][3] + bb + r.w;
        *(float4*)&out[ob] = o;
    }
}

extern "C" void kernel_launch(void* const* d_in, const int* in_sizes, int n_in,
                              void* d_out, int out_size){
    const float* x1  = (const float*)d_in[0];
    const float* x2  = (const float*)d_in[1];
    const float* q1w = (const float*)d_in[2];  const float* q1b = (const float*)d_in[3];
    const float* q2w = (const float*)d_in[4];  const float* q2b = (const float*)d_in[5];
    const float* k1w = (const float*)d_in[6];  const float* k1b = (const float*)d_in[7];
    const float* k2w = (const float*)d_in[8];  const float* k2b = (const float*)d_in[9];
    const float* v1w = (const float*)d_in[10]; const float* v1b = (const float*)d_in[11];
    const float* v2w = (const float*)d_in[12]; const float* v2b = (const float*)d_in[13];
    const float* rw  = (const float*)d_in[14]; const float* rb  = (const float*)d_in[15];
    const float* m1w = (const float*)d_in[16]; const float* m1b = (const float*)d_in[17];
    const float* m2w = (const float*)d_in[18]; const float* m2b = (const float*)d_in[19];
    const float* m3w = (const float*)d_in[20]; const float* m3b = (const float*)d_in[21];
    float* out = (float*)d_out;

    k_prep<<<800, 256>>>(rw, m1w, m3w);
    k_qkv1<<<1024, 256>>>(x1, x2, q1w, q1b, k1w, k1b, v1w, v1b);
    k_dws<<<dim3(32768, 3), 256>>>(q2w, q2b, k2w, k2b, v2w, v2b);
    k_kstats<<<256, 256>>>();
    k_zero<<<16, 256>>>();
    k_ctx<<<dim3(16, 16), 256>>>();
    k_att<<<dim3(128, 16), 256>>>();
    k_conv5<<<dim3(16, 16, 16), 256>>>(rb, out);
    k_gemm_m1<<<dim3(1024, 4, 4), 256>>>(out, m1b);
    k_m2dw<<<262144, 256>>>(m2w, m2b);
    k_gemm_m3<<<dim3(1024, 2, 4), 256>>>(m3b, out);
}